// round 12
// baseline (speedup 1.0000x reference)
#include <cuda_runtime.h>
#include <cuda_fp16.h>
#include <cstdint>

// ---------------------------------------------------------------------------
// Problem constants
// ---------------------------------------------------------------------------
#define BB 4
#define NN 2048
#define DD 512
#define HH 8
#define HD 64
#define TQ 128           // queries per CTA
#define TK 128           // keys per tile
#define NTILES (NN / TK) // 16

// exp(S/TEMP) = 2^(S * log2(e)/8)
#define CEXP 0.1803368801111244f

typedef unsigned long long u64;

// fp16 staging buffers (per-head contiguous layout: [(b*HH+h), n, hd])
__device__ __half g_qh[(size_t)BB * HH * NN * HD];
__device__ __half g_kh[(size_t)BB * HH * NN * HD];
__device__ __half g_vh[(size_t)BB * HH * NN * HD];
// attention output fp16: [(b*NN + n), d]
__device__ __half g_ah[(size_t)BB * NN * DD];
// W fp16 [n][k]
__device__ __half g_wh[(size_t)DD * DD];

#define SWZ(o) ((o) ^ (((o) >> 3) & 0x70))

// ---------------------------------------------------------------------------
// PTX helpers
// ---------------------------------------------------------------------------
__device__ __forceinline__ uint32_t smem_u32(const void* p) {
    uint32_t a;
    asm("{ .reg .u64 t; cvta.to.shared.u64 t, %1; cvt.u32.u64 %0, t; }" : "=r"(a) : "l"(p));
    return a;
}
__device__ __forceinline__ float ex2f(float x) {
    float y; asm("ex2.approx.f32 %0, %1;" : "=f"(y) : "f"(x)); return y;
}
__device__ __forceinline__ uint32_t cvt_f16x2(float hi, float lo) {
    uint32_t r; asm("cvt.rn.f16x2.f32 %0, %1, %2;" : "=r"(r) : "f"(hi), "f"(lo)); return r;
}
__device__ __forceinline__ void ldm4(uint32_t* r, uint32_t addr) {
    asm volatile("ldmatrix.sync.aligned.m8n8.x4.shared.b16 {%0,%1,%2,%3}, [%4];"
        : "=r"(r[0]), "=r"(r[1]), "=r"(r[2]), "=r"(r[3]) : "r"(addr));
}
__device__ __forceinline__ void ldm4t(uint32_t* r, uint32_t addr) {
    asm volatile("ldmatrix.sync.aligned.m8n8.x4.trans.shared.b16 {%0,%1,%2,%3}, [%4];"
        : "=r"(r[0]), "=r"(r[1]), "=r"(r[2]), "=r"(r[3]) : "r"(addr));
}
__device__ __forceinline__ void mma16816(float* c, const uint32_t* a, const uint32_t* b) {
    asm volatile("mma.sync.aligned.m16n8k16.row.col.f32.f16.f16.f32 "
        "{%0,%1,%2,%3}, {%4,%5,%6,%7}, {%8,%9}, {%0,%1,%2,%3};"
        : "+f"(c[0]), "+f"(c[1]), "+f"(c[2]), "+f"(c[3])
        : "r"(a[0]), "r"(a[1]), "r"(a[2]), "r"(a[3]), "r"(b[0]), "r"(b[1]));
}
__device__ __forceinline__ void cpa16(uint32_t dst, const void* src) {
    asm volatile("cp.async.cg.shared.global [%0], [%1], 16;"
        :: "r"(dst), "l"(__cvta_generic_to_global(src)) : "memory");
}
#define CPC()  asm volatile("cp.async.commit_group;" ::: "memory")
#define CPW0() asm volatile("cp.async.wait_group 0;" ::: "memory")
#define CPW1() asm volatile("cp.async.wait_group 1;" ::: "memory")

// ---------------------------------------------------------------------------
// Prep: fp32 -> fp16 conversion + per-head relayout (Q,K,V single fp16)
// grid (4096, 3), block 256. blockIdx.y: 0=K, 1=Q, 2=V
// ---------------------------------------------------------------------------
__global__ __launch_bounds__(256)
void prep_kernel(const float* __restrict__ Kg, const float* __restrict__ Qg,
                 const float* __restrict__ Vg)
{
    int i = blockIdx.x * 256 + threadIdx.x;   // float4 index
    int t = blockIdx.y;
    const float* src = (t == 0) ? Kg : (t == 1) ? Qg : Vg;
    float4 v = reinterpret_cast<const float4*>(src)[i];
    int d4 = i & 127, n = (i >> 7) & 2047, b = i >> 18;
    int h = d4 >> 4, hd4 = d4 & 15;
    size_t o = ((((size_t)b * HH + h) * NN + n) * HD + hd4 * 4);

    __half2 hA = __halves2half2(__float2half_rn(v.x), __float2half_rn(v.y));
    __half2 hB = __halves2half2(__float2half_rn(v.z), __float2half_rn(v.w));
    uint2 hw = make_uint2(*reinterpret_cast<uint32_t*>(&hA),
                          *reinterpret_cast<uint32_t*>(&hB));
    __half* dst = (t == 0) ? g_kh : (t == 1) ? g_qh : g_vh;
    *reinterpret_cast<uint2*>(dst + o) = hw;
}

__global__ __launch_bounds__(256)
void prep_w_kernel(const float* __restrict__ W)
{
    int i = blockIdx.x * 256 + threadIdx.x;   // float4 index, 65536 total
    float4 v = reinterpret_cast<const float4*>(W)[i];
    size_t o = (size_t)i * 4;
    __half2 hA = __halves2half2(__float2half_rn(v.x), __float2half_rn(v.y));
    __half2 hB = __halves2half2(__float2half_rn(v.z), __float2half_rn(v.w));
    *reinterpret_cast<uint2*>(g_wh + o) =
        make_uint2(*reinterpret_cast<uint32_t*>(&hA), *reinterpret_cast<uint32_t*>(&hB));
}

// ---------------------------------------------------------------------------
// Attention: mma.sync + cp.async double-buffered pipeline, fp16 QK (1 pass).
// grid (16, 8, 4), block 256 (8 warps, 16 q-rows each).
// smem: 2 stages x {k 16K, v 16K} = 64 KB -> 2 CTAs/SM.
// ---------------------------------------------------------------------------
#define STG 32768
#define OFF_V 16384

__global__ __launch_bounds__(256, 2)
void attn2_kernel()
{
    extern __shared__ char smem[];
    const uint32_t sb = smem_u32(smem);
    const int tid  = threadIdx.x;
    const int wid  = tid >> 5;
    const int lane = tid & 31;
    const int gid  = lane >> 2;
    const int tig  = lane & 3;
    const int g8   = lane >> 3;
    const int ri   = lane & 7;
    const int q0 = blockIdx.x * TQ;
    const int h  = blockIdx.y;
    const int b  = blockIdx.z;

    const size_t hb = (((size_t)b) * HH + h) * NN * HD;  // head base (halves)

    // ---- stage Q tile into stage-0 K buffer, hoist A-fragments
    {
        const __half* qs = g_qh + hb + (size_t)q0 * HD;
#pragma unroll
        for (int i = 0; i < 4; i++) {
            int ch = i * 256 + tid;          // 16B chunk index 0..1023
            cpa16(sb + SWZ(ch * 16), qs + ch * 8);
        }
        CPC(); CPW0();
    }
    __syncthreads();

    uint32_t qh[4][4];
    {
        int arow = wid * 16 + ((g8 & 1) << 3) + ri;
        int acol = (g8 >> 1) << 3;
#pragma unroll
        for (int ks = 0; ks < 4; ks++) {
            int co = (ks * 16 + acol) * 2;
            ldm4(qh[ks], sb + SWZ(arow * 128 + co));
        }
    }
    __syncthreads();

    float o_acc[8][4];
#pragma unroll
    for (int i = 0; i < 8; i++)
#pragma unroll
        for (int j = 0; j < 4; j++) o_acc[i][j] = 0.0f;
    float lsum0 = 0.0f, lsum1 = 0.0f;

#define LOADTILE(t, s) do { \
    const __half* _kh = g_kh + hb + (size_t)(t) * TK * HD; \
    const __half* _vh = g_vh + hb + (size_t)(t) * TK * HD; \
    uint32_t _sb2 = sb + (s) * STG; \
    _Pragma("unroll") \
    for (int _i = 0; _i < 4; _i++) { \
        int _ch = _i * 256 + tid; \
        uint32_t _d = SWZ(_ch * 16); \
        cpa16(_sb2 + _d, _kh + _ch * 8); \
        cpa16(_sb2 + OFF_V + _d, _vh + _ch * 8); \
    } \
    CPC(); } while (0)

    LOADTILE(0, 0);
    LOADTILE(1, 1);

    for (int t = 0; t < NTILES; t++) {
        if (t == NTILES - 1) { CPW0(); } else { CPW1(); }
        __syncthreads();
        const uint32_t su = sb + (t & 1) * STG;

#pragma unroll
        for (int c = 0; c < 4; c++) {
            float sc[4][4];
#pragma unroll
            for (int i = 0; i < 4; i++)
#pragma unroll
                for (int j = 0; j < 4; j++) sc[i][j] = 0.0f;

#pragma unroll
            for (int q = 0; q < 4; q++) {
                int nt = c * 4 + q;
                int brow = nt * 8 + ri;
                uint32_t r4[4], bh[4][2];
                ldm4(r4, su + SWZ(brow * 128 + g8 * 16));
                bh[0][0] = r4[0]; bh[0][1] = r4[1]; bh[1][0] = r4[2]; bh[1][1] = r4[3];
                ldm4(r4, su + SWZ(brow * 128 + 64 + g8 * 16));
                bh[2][0] = r4[0]; bh[2][1] = r4[1]; bh[3][0] = r4[2]; bh[3][1] = r4[3];
#pragma unroll
                for (int ks = 0; ks < 4; ks++) mma16816(sc[q], qh[ks], bh[ks]);
            }

            uint32_t pf[4][2];
#pragma unroll
            for (int q = 0; q < 4; q++) {
                float e0 = ex2f(sc[q][0] * CEXP);
                float e1 = ex2f(sc[q][1] * CEXP);
                float e2 = ex2f(sc[q][2] * CEXP);
                float e3 = ex2f(sc[q][3] * CEXP);
                lsum0 += e0 + e1;
                lsum1 += e2 + e3;
                pf[q][0] = cvt_f16x2(e1, e0);
                pf[q][1] = cvt_f16x2(e3, e2);
            }

#pragma unroll
            for (int jj = 0; jj < 2; jj++) {
                uint32_t pa[4] = { pf[2 * jj][0], pf[2 * jj][1],
                                   pf[2 * jj + 1][0], pf[2 * jj + 1][1] };
                int vrow = (c * 2 + jj) * 16 + ((g8 & 1) << 3) + ri;
#pragma unroll
                for (int nvp = 0; nvp < 4; nvp++) {
                    int vchunk = nvp * 16 + ((g8 >> 1) << 3);
                    uint32_t r4[4];
                    ldm4t(r4, su + OFF_V + SWZ(vrow * 128 + vchunk * 2));
                    mma16816(o_acc[nvp * 2 + 0], pa, r4 + 0);
                    mma16816(o_acc[nvp * 2 + 1], pa, r4 + 2);
                }
            }
        }
        __syncthreads();
        if (t + 2 < NTILES) LOADTILE(t + 2, t & 1);
    }

    // ---- finalize (fp16 output only)
    lsum0 += __shfl_xor_sync(0xffffffffu, lsum0, 1);
    lsum0 += __shfl_xor_sync(0xffffffffu, lsum0, 2);
    lsum1 += __shfl_xor_sync(0xffffffffu, lsum1, 1);
    lsum1 += __shfl_xor_sync(0xffffffffu, lsum1, 2);
    const float inv0 = 1.0f / lsum0;
    const float inv1 = 1.0f / lsum1;

    const int wr0 = q0 + wid * 16 + gid;
    size_t base0 = ((size_t)(b * NN + wr0)) * DD + h * HD;
    size_t base1 = base0 + (size_t)8 * DD;
#pragma unroll
    for (int nv = 0; nv < 8; nv++) {
        int col = nv * 8 + tig * 2;
        *reinterpret_cast<uint32_t*>(g_ah + base0 + col) =
            cvt_f16x2(o_acc[nv][1] * inv0, o_acc[nv][0] * inv0);
        *reinterpret_cast<uint32_t*>(g_ah + base1 + col) =
            cvt_f16x2(o_acc[nv][3] * inv1, o_acc[nv][2] * inv1);
    }
}

// ---------------------------------------------------------------------------
// Projection: C[m][n] = A[m][:] . W[n][:] + bias[n], single-pass fp16 mma.
// grid (8, 64): 64-col x 128-row tiles. block 256 (8 warps, 32x32 warp tile).
// k-chunk 64. smem: 2 stages x {A 16K, W 8K} = 48 KB -> 3 CTAs/SM target.
// ---------------------------------------------------------------------------
#define PSTG 24576
#define POFF_W 16384

__global__ __launch_bounds__(256, 3)
void proj3_kernel(const float* __restrict__ bias, float* __restrict__ C)
{
    extern __shared__ char smem[];
    const uint32_t sb = smem_u32(smem);
    const int tid  = threadIdx.x;
    const int wid  = tid >> 5;
    const int lane = tid & 31;
    const int gid  = lane >> 2;
    const int tig  = lane & 3;
    const int g8   = lane >> 3;
    const int ri   = lane & 7;
    const int n0 = blockIdx.x * 64;
    const int m0 = blockIdx.y * 128;
    const int warp_m = (wid & 3) * 32;
    const int warp_n = (wid >> 2) * 32;

    // k-chunk = 64 halves = 128 B/row (exactly one SW128 row)
#define PLOAD(kc, s) do { \
    uint32_t _sb2 = sb + (s) * PSTG; \
    _Pragma("unroll") \
    for (int _i = 0; _i < 4; _i++) { \
        int _slot = _i * 256 + tid; \
        int _row = _slot >> 3, _c8 = _slot & 7; \
        cpa16(_sb2 + SWZ(_row * 128 + _c8 * 16), \
              g_ah + (size_t)(m0 + _row) * DD + (kc) * 64 + _c8 * 8); \
    } \
    _Pragma("unroll") \
    for (int _i = 0; _i < 2; _i++) { \
        int _slot = _i * 256 + tid; \
        int _row = _slot >> 3, _c8 = _slot & 7; \
        cpa16(_sb2 + POFF_W + SWZ(_row * 128 + _c8 * 16), \
              g_wh + (size_t)(n0 + _row) * DD + (kc) * 64 + _c8 * 8); \
    } \
    CPC(); } while (0)

    float acc[2][4][4];
#pragma unroll
    for (int m = 0; m < 2; m++)
#pragma unroll
        for (int nb = 0; nb < 4; nb++)
#pragma unroll
            for (int j = 0; j < 4; j++) acc[m][nb][j] = 0.0f;

    PLOAD(0, 0);
    PLOAD(1, 1);

    for (int kc = 0; kc < 8; kc++) {
        if (kc == 7) { CPW0(); } else { CPW1(); }
        __syncthreads();
        const uint32_t su = sb + (kc & 1) * PSTG;

        uint32_t ah[2][4][4];
#pragma unroll
        for (int m = 0; m < 2; m++) {
            int arow = warp_m + m * 16 + ((g8 & 1) << 3) + ri;
#pragma unroll
            for (int ks = 0; ks < 4; ks++) {
                ldm4(ah[m][ks], su + SWZ(arow * 128 + ks * 32 + ((g8 >> 1) << 4)));
            }
        }
#pragma unroll
        for (int nb = 0; nb < 4; nb++) {
            int brow = warp_n + nb * 8 + ri;
            uint32_t w0[4], w1[4];
            ldm4(w0, su + POFF_W + SWZ(brow * 128 + g8 * 16));
            ldm4(w1, su + POFF_W + SWZ(brow * 128 + 64 + g8 * 16));
#pragma unroll
            for (int m = 0; m < 2; m++) {
                mma16816(acc[m][nb], ah[m][0], w0 + 0);
                mma16816(acc[m][nb], ah[m][1], w0 + 2);
                mma16816(acc[m][nb], ah[m][2], w1 + 0);
                mma16816(acc[m][nb], ah[m][3], w1 + 2);
            }
        }
        __syncthreads();
        if (kc + 2 < 8) PLOAD(kc + 2, kc & 1);
    }

#pragma unroll
    for (int m = 0; m < 2; m++) {
        int r0 = m0 + warp_m + m * 16 + gid;
#pragma unroll
        for (int nb = 0; nb < 4; nb++) {
            int col = n0 + warp_n + nb * 8 + tig * 2;
            float2 bv = *reinterpret_cast<const float2*>(bias + col);
            float2 v0 = make_float2(acc[m][nb][0] + bv.x, acc[m][nb][1] + bv.y);
            float2 v1 = make_float2(acc[m][nb][2] + bv.x, acc[m][nb][3] + bv.y);
            *reinterpret_cast<float2*>(C + (size_t)r0 * DD + col) = v0;
            *reinterpret_cast<float2*>(C + (size_t)(r0 + 8) * DD + col) = v1;
        }
    }
}

// ---------------------------------------------------------------------------
extern "C" void kernel_launch(void* const* d_in, const int* in_sizes, int n_in,
                              void* d_out, int out_size)
{
    const float* keys    = (const float*)d_in[0];
    const float* queries = (const float*)d_in[1];
    const float* values  = (const float*)d_in[2];
    const float* W_comb  = (const float*)d_in[3];
    const float* b_comb  = (const float*)d_in[4];
    float* out = (float*)d_out;

    cudaFuncSetAttribute(attn2_kernel,
                         cudaFuncAttributeMaxDynamicSharedMemorySize, 2 * STG);
    cudaFuncSetAttribute(proj3_kernel,
                         cudaFuncAttributeMaxDynamicSharedMemorySize, 2 * PSTG);

    prep_kernel<<<dim3(4096, 3), 256>>>(keys, queries, values);
    prep_w_kernel<<<256, 256>>>(W_comb);

    dim3 agrid(NN / TQ, HH, BB);
    attn2_kernel<<<agrid, 256, 2 * STG>>>();

    dim3 pgrid(DD / 64, (BB * NN) / 128);
    proj3_kernel<<<pgrid, 256, 2 * PSTG>>>(b_comb, out);
}

// round 13
// speedup vs baseline: 1.4681x; 1.4681x over previous
#include <cuda_runtime.h>
#include <cuda_fp16.h>
#include <cstdint>

// ---------------------------------------------------------------------------
// Problem constants
// ---------------------------------------------------------------------------
#define BB 4
#define NN 2048
#define DD 512
#define HH 8
#define HD 64
#define TQ 128           // queries per CTA
#define TK 128           // keys per tile
#define NTILES (NN / TK) // 16

// exp(S/TEMP) = 2^(S * log2(e)/8)
#define CEXP 0.1803368801111244f

typedef unsigned long long u64;

// fp16 staging buffers (per-head contiguous layout: [(b*HH+h), n, hd])
__device__ __half g_qh[(size_t)BB * HH * NN * HD];
__device__ __half g_kh[(size_t)BB * HH * NN * HD];
__device__ __half g_vh[(size_t)BB * HH * NN * HD];
// attention output fp16: [(b*NN + n), d]
__device__ __half g_ah[(size_t)BB * NN * DD];
// W fp16 [n][k]
__device__ __half g_wh[(size_t)DD * DD];

#define SWZ(o) ((o) ^ (((o) >> 3) & 0x70))

// ---------------------------------------------------------------------------
// PTX helpers
// ---------------------------------------------------------------------------
__device__ __forceinline__ uint32_t smem_u32(const void* p) {
    uint32_t a;
    asm("{ .reg .u64 t; cvta.to.shared.u64 t, %1; cvt.u32.u64 %0, t; }" : "=r"(a) : "l"(p));
    return a;
}
__device__ __forceinline__ float ex2f(float x) {
    float y; asm("ex2.approx.f32 %0, %1;" : "=f"(y) : "f"(x)); return y;
}
__device__ __forceinline__ uint32_t cvt_f16x2(float hi, float lo) {
    uint32_t r; asm("cvt.rn.f16x2.f32 %0, %1, %2;" : "=r"(r) : "f"(hi), "f"(lo)); return r;
}
__device__ __forceinline__ void ldm4(uint32_t* r, uint32_t addr) {
    asm volatile("ldmatrix.sync.aligned.m8n8.x4.shared.b16 {%0,%1,%2,%3}, [%4];"
        : "=r"(r[0]), "=r"(r[1]), "=r"(r[2]), "=r"(r[3]) : "r"(addr));
}
__device__ __forceinline__ void ldm4t(uint32_t* r, uint32_t addr) {
    asm volatile("ldmatrix.sync.aligned.m8n8.x4.trans.shared.b16 {%0,%1,%2,%3}, [%4];"
        : "=r"(r[0]), "=r"(r[1]), "=r"(r[2]), "=r"(r[3]) : "r"(addr));
}
__device__ __forceinline__ void mma16816(float* c, const uint32_t* a, const uint32_t* b) {
    asm volatile("mma.sync.aligned.m16n8k16.row.col.f32.f16.f16.f32 "
        "{%0,%1,%2,%3}, {%4,%5,%6,%7}, {%8,%9}, {%0,%1,%2,%3};"
        : "+f"(c[0]), "+f"(c[1]), "+f"(c[2]), "+f"(c[3])
        : "r"(a[0]), "r"(a[1]), "r"(a[2]), "r"(a[3]), "r"(b[0]), "r"(b[1]));
}
__device__ __forceinline__ void cpa16(uint32_t dst, const void* src) {
    asm volatile("cp.async.cg.shared.global [%0], [%1], 16;"
        :: "r"(dst), "l"(__cvta_generic_to_global(src)) : "memory");
}
#define CPC()  asm volatile("cp.async.commit_group;" ::: "memory")
#define CPW0() asm volatile("cp.async.wait_group 0;" ::: "memory")
#define CPW1() asm volatile("cp.async.wait_group 1;" ::: "memory")

// ---------------------------------------------------------------------------
// Prep: fp32 -> fp16 conversion + per-head relayout; W folded in (y == 3).
// grid (4096, 4), block 256. blockIdx.y: 0=K, 1=Q, 2=V, 3=W (first 256 blocks)
// ---------------------------------------------------------------------------
__global__ __launch_bounds__(256)
void prep_kernel(const float* __restrict__ Kg, const float* __restrict__ Qg,
                 const float* __restrict__ Vg, const float* __restrict__ Wg)
{
    int t = blockIdx.y;
    if (t == 3) {
        if (blockIdx.x >= 256) return;
        int i = blockIdx.x * 256 + threadIdx.x;   // float4 index, 65536 total
        float4 v = reinterpret_cast<const float4*>(Wg)[i];
        __half2 hA = __halves2half2(__float2half_rn(v.x), __float2half_rn(v.y));
        __half2 hB = __halves2half2(__float2half_rn(v.z), __float2half_rn(v.w));
        *reinterpret_cast<uint2*>(g_wh + (size_t)i * 4) =
            make_uint2(*reinterpret_cast<uint32_t*>(&hA),
                       *reinterpret_cast<uint32_t*>(&hB));
        return;
    }
    int i = blockIdx.x * 256 + threadIdx.x;   // float4 index
    const float* src = (t == 0) ? Kg : (t == 1) ? Qg : Vg;
    float4 v = reinterpret_cast<const float4*>(src)[i];
    int d4 = i & 127, n = (i >> 7) & 2047, b = i >> 18;
    int h = d4 >> 4, hd4 = d4 & 15;
    size_t o = ((((size_t)b * HH + h) * NN + n) * HD + hd4 * 4);

    __half2 hA = __halves2half2(__float2half_rn(v.x), __float2half_rn(v.y));
    __half2 hB = __halves2half2(__float2half_rn(v.z), __float2half_rn(v.w));
    uint2 hw = make_uint2(*reinterpret_cast<uint32_t*>(&hA),
                          *reinterpret_cast<uint32_t*>(&hB));
    __half* dst = (t == 0) ? g_kh : (t == 1) ? g_qh : g_vh;
    *reinterpret_cast<uint2*>(dst + o) = hw;
}

// ---------------------------------------------------------------------------
// Attention: mma.sync + 3-stage cp.async pipeline, fp16 QK (1 pass).
// grid (16, 8, 4), block 256 (8 warps, 16 q-rows each).
// smem: 3 stages x {k 16K, v 16K} = 96 KB -> 2 CTAs/SM.
// One barrier per tile (3-stage rotation makes the trailing barrier redundant:
// ldmatrix reads are synchronous, so the iteration-start barrier proves all
// warps finished reading stage (t-1)%3 == (t+2)%3 before it is refilled).
// ---------------------------------------------------------------------------
#define ASTG 32768
#define OFF_V 16384

__global__ __launch_bounds__(256, 2)
void attn2_kernel()
{
    extern __shared__ char smem[];
    const uint32_t sb = smem_u32(smem);
    const int tid  = threadIdx.x;
    const int wid  = tid >> 5;
    const int lane = tid & 31;
    const int gid  = lane >> 2;
    const int tig  = lane & 3;
    const int g8   = lane >> 3;
    const int ri   = lane & 7;
    const int q0 = blockIdx.x * TQ;
    const int h  = blockIdx.y;
    const int b  = blockIdx.z;

    const size_t hb = (((size_t)b) * HH + h) * NN * HD;  // head base (halves)

    // ---- stage Q tile into stage-0 K buffer, hoist A-fragments
    {
        const __half* qs = g_qh + hb + (size_t)q0 * HD;
#pragma unroll
        for (int i = 0; i < 4; i++) {
            int ch = i * 256 + tid;          // 16B chunk index 0..1023
            cpa16(sb + SWZ(ch * 16), qs + ch * 8);
        }
        CPC(); CPW0();
    }
    __syncthreads();

    uint32_t qh[4][4];
    {
        int arow = wid * 16 + ((g8 & 1) << 3) + ri;
        int acol = (g8 >> 1) << 3;
#pragma unroll
        for (int ks = 0; ks < 4; ks++) {
            int co = (ks * 16 + acol) * 2;
            ldm4(qh[ks], sb + SWZ(arow * 128 + co));
        }
    }
    __syncthreads();

    float o_acc[8][4];
#pragma unroll
    for (int i = 0; i < 8; i++)
#pragma unroll
        for (int j = 0; j < 4; j++) o_acc[i][j] = 0.0f;
    float lsum0 = 0.0f, lsum1 = 0.0f;

#define LOADTILE(t, s) do { \
    const __half* _kh = g_kh + hb + (size_t)(t) * TK * HD; \
    const __half* _vh = g_vh + hb + (size_t)(t) * TK * HD; \
    uint32_t _sb2 = sb + (s) * ASTG; \
    _Pragma("unroll") \
    for (int _i = 0; _i < 4; _i++) { \
        int _ch = _i * 256 + tid; \
        uint32_t _d = SWZ(_ch * 16); \
        cpa16(_sb2 + _d, _kh + _ch * 8); \
        cpa16(_sb2 + OFF_V + _d, _vh + _ch * 8); \
    } \
    CPC(); } while (0)

    LOADTILE(0, 0);
    LOADTILE(1, 1);

    for (int t = 0; t < NTILES; t++) {
        if (t == NTILES - 1) { CPW0(); } else { CPW1(); }
        __syncthreads();
        if (t + 2 < NTILES) LOADTILE(t + 2, (t + 2) % 3);
        const uint32_t su = sb + (t % 3) * ASTG;

#pragma unroll
        for (int c = 0; c < 4; c++) {
            float sc[4][4];
#pragma unroll
            for (int i = 0; i < 4; i++)
#pragma unroll
                for (int j = 0; j < 4; j++) sc[i][j] = 0.0f;

#pragma unroll
            for (int q = 0; q < 4; q++) {
                int nt = c * 4 + q;
                int brow = nt * 8 + ri;
                uint32_t r4[4], bh[4][2];
                ldm4(r4, su + SWZ(brow * 128 + g8 * 16));
                bh[0][0] = r4[0]; bh[0][1] = r4[1]; bh[1][0] = r4[2]; bh[1][1] = r4[3];
                ldm4(r4, su + SWZ(brow * 128 + 64 + g8 * 16));
                bh[2][0] = r4[0]; bh[2][1] = r4[1]; bh[3][0] = r4[2]; bh[3][1] = r4[3];
#pragma unroll
                for (int ks = 0; ks < 4; ks++) mma16816(sc[q], qh[ks], bh[ks]);
            }

            uint32_t pf[4][2];
#pragma unroll
            for (int q = 0; q < 4; q++) {
                float e0 = ex2f(sc[q][0] * CEXP);
                float e1 = ex2f(sc[q][1] * CEXP);
                float e2 = ex2f(sc[q][2] * CEXP);
                float e3 = ex2f(sc[q][3] * CEXP);
                lsum0 += e0 + e1;
                lsum1 += e2 + e3;
                pf[q][0] = cvt_f16x2(e1, e0);
                pf[q][1] = cvt_f16x2(e3, e2);
            }

#pragma unroll
            for (int jj = 0; jj < 2; jj++) {
                uint32_t pa[4] = { pf[2 * jj][0], pf[2 * jj][1],
                                   pf[2 * jj + 1][0], pf[2 * jj + 1][1] };
                int vrow = (c * 2 + jj) * 16 + ((g8 & 1) << 3) + ri;
#pragma unroll
                for (int nvp = 0; nvp < 4; nvp++) {
                    int vchunk = nvp * 16 + ((g8 >> 1) << 3);
                    uint32_t r4[4];
                    ldm4t(r4, su + OFF_V + SWZ(vrow * 128 + vchunk * 2));
                    mma16816(o_acc[nvp * 2 + 0], pa, r4 + 0);
                    mma16816(o_acc[nvp * 2 + 1], pa, r4 + 2);
                }
            }
        }
        // no trailing barrier: 3-stage rotation keeps readers/writers disjoint
    }

    // ---- finalize (fp16 output only)
    lsum0 += __shfl_xor_sync(0xffffffffu, lsum0, 1);
    lsum0 += __shfl_xor_sync(0xffffffffu, lsum0, 2);
    lsum1 += __shfl_xor_sync(0xffffffffu, lsum1, 1);
    lsum1 += __shfl_xor_sync(0xffffffffu, lsum1, 2);
    const float inv0 = 1.0f / lsum0;
    const float inv1 = 1.0f / lsum1;

    const int wr0 = q0 + wid * 16 + gid;
    size_t base0 = ((size_t)(b * NN + wr0)) * DD + h * HD;
    size_t base1 = base0 + (size_t)8 * DD;
#pragma unroll
    for (int nv = 0; nv < 8; nv++) {
        int col = nv * 8 + tig * 2;
        *reinterpret_cast<uint32_t*>(g_ah + base0 + col) =
            cvt_f16x2(o_acc[nv][1] * inv0, o_acc[nv][0] * inv0);
        *reinterpret_cast<uint32_t*>(g_ah + base1 + col) =
            cvt_f16x2(o_acc[nv][3] * inv1, o_acc[nv][2] * inv1);
    }
}

// ---------------------------------------------------------------------------
// Projection: C[m][n] = A[m][:] . W[n][:] + bias[n], single-pass fp16 mma.
// grid (8, 64): 64-col x 128-row tiles. block 256 (8 warps, 32x32 warp tile).
// k-chunk 64. smem: 3 stages x {A 16K, W 8K} = 72 KB -> 3 CTAs/SM.
// ---------------------------------------------------------------------------
#define PSTG 24576
#define POFF_W 16384

__global__ __launch_bounds__(256, 3)
void proj3_kernel(const float* __restrict__ bias, float* __restrict__ C)
{
    extern __shared__ char smem[];
    const uint32_t sb = smem_u32(smem);
    const int tid  = threadIdx.x;
    const int wid  = tid >> 5;
    const int lane = tid & 31;
    const int gid  = lane >> 2;
    const int tig  = lane & 3;
    const int g8   = lane >> 3;
    const int ri   = lane & 7;
    const int n0 = blockIdx.x * 64;
    const int m0 = blockIdx.y * 128;
    const int warp_m = (wid & 3) * 32;
    const int warp_n = (wid >> 2) * 32;

    // k-chunk = 64 halves = 128 B/row (exactly one SW128 row)
#define PLOAD(kc, s) do { \
    uint32_t _sb2 = sb + (s) * PSTG; \
    _Pragma("unroll") \
    for (int _i = 0; _i < 4; _i++) { \
        int _slot = _i * 256 + tid; \
        int _row = _slot >> 3, _c8 = _slot & 7; \
        cpa16(_sb2 + SWZ(_row * 128 + _c8 * 16), \
              g_ah + (size_t)(m0 + _row) * DD + (kc) * 64 + _c8 * 8); \
    } \
    _Pragma("unroll") \
    for (int _i = 0; _i < 2; _i++) { \
        int _slot = _i * 256 + tid; \
        int _row = _slot >> 3, _c8 = _slot & 7; \
        cpa16(_sb2 + POFF_W + SWZ(_row * 128 + _c8 * 16), \
              g_wh + (size_t)(n0 + _row) * DD + (kc) * 64 + _c8 * 8); \
    } \
    CPC(); } while (0)

    float acc[2][4][4];
#pragma unroll
    for (int m = 0; m < 2; m++)
#pragma unroll
        for (int nb = 0; nb < 4; nb++)
#pragma unroll
            for (int j = 0; j < 4; j++) acc[m][nb][j] = 0.0f;

    PLOAD(0, 0);
    PLOAD(1, 1);

    for (int kc = 0; kc < 8; kc++) {
        if (kc == 7) { CPW0(); } else { CPW1(); }
        __syncthreads();
        if (kc + 2 < 8) PLOAD(kc + 2, (kc + 2) % 3);
        const uint32_t su = sb + (kc % 3) * PSTG;

        uint32_t ah[2][4][4];
#pragma unroll
        for (int m = 0; m < 2; m++) {
            int arow = warp_m + m * 16 + ((g8 & 1) << 3) + ri;
#pragma unroll
            for (int ks = 0; ks < 4; ks++) {
                ldm4(ah[m][ks], su + SWZ(arow * 128 + ks * 32 + ((g8 >> 1) << 4)));
            }
        }
#pragma unroll
        for (int nb = 0; nb < 4; nb++) {
            int brow = warp_n + nb * 8 + ri;
            uint32_t w0[4], w1[4];
            ldm4(w0, su + POFF_W + SWZ(brow * 128 + g8 * 16));
            ldm4(w1, su + POFF_W + SWZ(brow * 128 + 64 + g8 * 16));
#pragma unroll
            for (int m = 0; m < 2; m++) {
                mma16816(acc[m][nb], ah[m][0], w0 + 0);
                mma16816(acc[m][nb], ah[m][1], w0 + 2);
                mma16816(acc[m][nb], ah[m][2], w1 + 0);
                mma16816(acc[m][nb], ah[m][3], w1 + 2);
            }
        }
        // no trailing barrier (3-stage rotation)
    }

#pragma unroll
    for (int m = 0; m < 2; m++) {
        int r0 = m0 + warp_m + m * 16 + gid;
#pragma unroll
        for (int nb = 0; nb < 4; nb++) {
            int col = n0 + warp_n + nb * 8 + tig * 2;
            float2 bv = *reinterpret_cast<const float2*>(bias + col);
            float2 v0 = make_float2(acc[m][nb][0] + bv.x, acc[m][nb][1] + bv.y);
            float2 v1 = make_float2(acc[m][nb][2] + bv.x, acc[m][nb][3] + bv.y);
            *reinterpret_cast<float2*>(C + (size_t)r0 * DD + col) = v0;
            *reinterpret_cast<float2*>(C + (size_t)(r0 + 8) * DD + col) = v1;
        }
    }
}

// ---------------------------------------------------------------------------
extern "C" void kernel_launch(void* const* d_in, const int* in_sizes, int n_in,
                              void* d_out, int out_size)
{
    const float* keys    = (const float*)d_in[0];
    const float* queries = (const float*)d_in[1];
    const float* values  = (const float*)d_in[2];
    const float* W_comb  = (const float*)d_in[3];
    const float* b_comb  = (const float*)d_in[4];
    float* out = (float*)d_out;

    cudaFuncSetAttribute(attn2_kernel,
                         cudaFuncAttributeMaxDynamicSharedMemorySize, 3 * ASTG);
    cudaFuncSetAttribute(proj3_kernel,
                         cudaFuncAttributeMaxDynamicSharedMemorySize, 3 * PSTG);

    prep_kernel<<<dim3(4096, 4), 256>>>(keys, queries, values, W_comb);

    dim3 agrid(NN / TQ, HH, BB);
    attn2_kernel<<<agrid, 256, 3 * ASTG>>>();

    dim3 pgrid(DD / 64, (BB * NN) / 128);
    proj3_kernel<<<pgrid, 256, 3 * PSTG>>>(b_comb, out);
}

// round 15
// speedup vs baseline: 1.4866x; 1.0126x over previous
#include <cuda_runtime.h>
#include <cuda_fp16.h>
#include <cstdint>

// ---------------------------------------------------------------------------
// Problem constants
// ---------------------------------------------------------------------------
#define BB 4
#define NN 2048
#define DD 512
#define HH 8
#define HD 64
#define TQ 128           // queries per CTA
#define TK 128           // keys per tile
#define NTILES (NN / TK) // 16

// exp(S/TEMP) = 2^(S * log2(e)/8)
#define CEXP 0.1803368801111244f

typedef unsigned long long u64;

// fp16 staging buffers (per-head contiguous layout: [(b*HH+h), n, hd])
__device__ __half g_qh[(size_t)BB * HH * NN * HD];
__device__ __half g_kh[(size_t)BB * HH * NN * HD];
__device__ __half g_vh[(size_t)BB * HH * NN * HD];
// attention output fp16: [(b*NN + n), d]
__device__ __half g_ah[(size_t)BB * NN * DD];
// W fp16 [n][k]
__device__ __half g_wh[(size_t)DD * DD];

#define SWZ(o) ((o) ^ (((o) >> 3) & 0x70))

// ---------------------------------------------------------------------------
// PTX helpers
// ---------------------------------------------------------------------------
__device__ __forceinline__ uint32_t smem_u32(const void* p) {
    uint32_t a;
    asm("{ .reg .u64 t; cvta.to.shared.u64 t, %1; cvt.u32.u64 %0, t; }" : "=r"(a) : "l"(p));
    return a;
}
__device__ __forceinline__ float ex2f(float x) {
    float y; asm("ex2.approx.f32 %0, %1;" : "=f"(y) : "f"(x)); return y;
}
__device__ __forceinline__ uint32_t cvt_f16x2(float hi, float lo) {
    uint32_t r; asm("cvt.rn.f16x2.f32 %0, %1, %2;" : "=r"(r) : "f"(hi), "f"(lo)); return r;
}
__device__ __forceinline__ void ldm4(uint32_t* r, uint32_t addr) {
    asm volatile("ldmatrix.sync.aligned.m8n8.x4.shared.b16 {%0,%1,%2,%3}, [%4];"
        : "=r"(r[0]), "=r"(r[1]), "=r"(r[2]), "=r"(r[3]) : "r"(addr));
}
__device__ __forceinline__ void ldm4t(uint32_t* r, uint32_t addr) {
    asm volatile("ldmatrix.sync.aligned.m8n8.x4.trans.shared.b16 {%0,%1,%2,%3}, [%4];"
        : "=r"(r[0]), "=r"(r[1]), "=r"(r[2]), "=r"(r[3]) : "r"(addr));
}
__device__ __forceinline__ void mma16816(float* c, const uint32_t* a, const uint32_t* b) {
    asm volatile("mma.sync.aligned.m16n8k16.row.col.f32.f16.f16.f32 "
        "{%0,%1,%2,%3}, {%4,%5,%6,%7}, {%8,%9}, {%0,%1,%2,%3};"
        : "+f"(c[0]), "+f"(c[1]), "+f"(c[2]), "+f"(c[3])
        : "r"(a[0]), "r"(a[1]), "r"(a[2]), "r"(a[3]), "r"(b[0]), "r"(b[1]));
}
// fp16-accumulator variant (2x rate expected)
__device__ __forceinline__ void mma16816h(uint32_t* c, const uint32_t* a, const uint32_t* b) {
    asm volatile("mma.sync.aligned.m16n8k16.row.col.f16.f16.f16.f16 "
        "{%0,%1}, {%2,%3,%4,%5}, {%6,%7}, {%0,%1};"
        : "+r"(c[0]), "+r"(c[1])
        : "r"(a[0]), "r"(a[1]), "r"(a[2]), "r"(a[3]), "r"(b[0]), "r"(b[1]));
}
__device__ __forceinline__ void cpa16(uint32_t dst, const void* src) {
    asm volatile("cp.async.cg.shared.global [%0], [%1], 16;"
        :: "r"(dst), "l"(__cvta_generic_to_global(src)) : "memory");
}
#define CPC()  asm volatile("cp.async.commit_group;" ::: "memory")
#define CPW0() asm volatile("cp.async.wait_group 0;" ::: "memory")
#define CPW1() asm volatile("cp.async.wait_group 1;" ::: "memory")

// ---------------------------------------------------------------------------
// Prep: fp32 -> fp16 conversion + per-head relayout; 2 float4 per thread.
// grid (2048, 4), block 256. blockIdx.y: 0=K, 1=Q, 2=V, 3=W (first 128 blocks)
// ---------------------------------------------------------------------------
__global__ __launch_bounds__(256)
void prep_kernel(const float* __restrict__ Kg, const float* __restrict__ Qg,
                 const float* __restrict__ Vg, const float* __restrict__ Wg)
{
    int t = blockIdx.y;
    if (t == 3) {
        if (blockIdx.x >= 128) return;
        int i0 = blockIdx.x * 512 + threadIdx.x * 2;
#pragma unroll
        for (int j = 0; j < 2; j++) {
            int i = i0 + j;
            float4 v = reinterpret_cast<const float4*>(Wg)[i];
            __half2 hA = __halves2half2(__float2half_rn(v.x), __float2half_rn(v.y));
            __half2 hB = __halves2half2(__float2half_rn(v.z), __float2half_rn(v.w));
            *reinterpret_cast<uint2*>(g_wh + (size_t)i * 4) =
                make_uint2(*reinterpret_cast<uint32_t*>(&hA),
                           *reinterpret_cast<uint32_t*>(&hB));
        }
        return;
    }
    const float* src = (t == 0) ? Kg : (t == 1) ? Qg : Vg;
    __half* dst = (t == 0) ? g_kh : (t == 1) ? g_qh : g_vh;
    int i0 = blockIdx.x * 512 + threadIdx.x * 2;
#pragma unroll
    for (int j = 0; j < 2; j++) {
        int i = i0 + j;
        float4 v = reinterpret_cast<const float4*>(src)[i];
        int d4 = i & 127, n = (i >> 7) & 2047, b = i >> 18;
        int h = d4 >> 4, hd4 = d4 & 15;
        size_t o = ((((size_t)b * HH + h) * NN + n) * HD + hd4 * 4);
        __half2 hA = __halves2half2(__float2half_rn(v.x), __float2half_rn(v.y));
        __half2 hB = __halves2half2(__float2half_rn(v.z), __float2half_rn(v.w));
        *reinterpret_cast<uint2*>(dst + o) =
            make_uint2(*reinterpret_cast<uint32_t*>(&hA),
                       *reinterpret_cast<uint32_t*>(&hB));
    }
}

// ---------------------------------------------------------------------------
// Attention: mma.sync + 3-stage cp.async pipeline.
// QK: fp16 in / fp32 accum (1 pass). PV: fp16 accum per 128-key tile, flushed
// to fp32 master accumulators each tile (error ~3.5e-4 contribution).
// grid (16, 8, 4), block 256 (8 warps, 16 q-rows each).
// smem: 3 stages x {k 16K, v 16K} = 96 KB -> 2 CTAs/SM.
// ---------------------------------------------------------------------------
#define ASTG 32768
#define OFF_V 16384

__global__ __launch_bounds__(256, 2)
void attn2_kernel()
{
    extern __shared__ char smem[];
    const uint32_t sb = smem_u32(smem);
    const int tid  = threadIdx.x;
    const int wid  = tid >> 5;
    const int lane = tid & 31;
    const int gid  = lane >> 2;
    const int tig  = lane & 3;
    const int g8   = lane >> 3;
    const int ri   = lane & 7;
    const int q0 = blockIdx.x * TQ;
    const int h  = blockIdx.y;
    const int b  = blockIdx.z;

    const size_t hb = (((size_t)b) * HH + h) * NN * HD;  // head base (halves)

    // ---- stage Q tile into stage-0 K buffer, hoist A-fragments
    {
        const __half* qs = g_qh + hb + (size_t)q0 * HD;
#pragma unroll
        for (int i = 0; i < 4; i++) {
            int ch = i * 256 + tid;          // 16B chunk index 0..1023
            cpa16(sb + SWZ(ch * 16), qs + ch * 8);
        }
        CPC(); CPW0();
    }
    __syncthreads();

    uint32_t qh[4][4];
    {
        int arow = wid * 16 + ((g8 & 1) << 3) + ri;
        int acol = (g8 >> 1) << 3;
#pragma unroll
        for (int ks = 0; ks < 4; ks++) {
            int co = (ks * 16 + acol) * 2;
            ldm4(qh[ks], sb + SWZ(arow * 128 + co));
        }
    }
    __syncthreads();

    float o_acc[8][4];
#pragma unroll
    for (int i = 0; i < 8; i++)
#pragma unroll
        for (int j = 0; j < 4; j++) o_acc[i][j] = 0.0f;
    float lsum0 = 0.0f, lsum1 = 0.0f;

#define LOADTILE(t, s) do { \
    const __half* _kh = g_kh + hb + (size_t)(t) * TK * HD; \
    const __half* _vh = g_vh + hb + (size_t)(t) * TK * HD; \
    uint32_t _sb2 = sb + (s) * ASTG; \
    _Pragma("unroll") \
    for (int _i = 0; _i < 4; _i++) { \
        int _ch = _i * 256 + tid; \
        uint32_t _d = SWZ(_ch * 16); \
        cpa16(_sb2 + _d, _kh + _ch * 8); \
        cpa16(_sb2 + OFF_V + _d, _vh + _ch * 8); \
    } \
    CPC(); } while (0)

    LOADTILE(0, 0);
    LOADTILE(1, 1);

    for (int t = 0; t < NTILES; t++) {
        if (t == NTILES - 1) { CPW0(); } else { CPW1(); }
        __syncthreads();
        if (t + 2 < NTILES) LOADTILE(t + 2, (t + 2) % 3);
        const uint32_t su = sb + (t % 3) * ASTG;

        // per-tile fp16 PV accumulators
        uint32_t o16[8][2];
#pragma unroll
        for (int i = 0; i < 8; i++) { o16[i][0] = 0u; o16[i][1] = 0u; }

#pragma unroll
        for (int c = 0; c < 4; c++) {
            float sc[4][4];
#pragma unroll
            for (int i = 0; i < 4; i++)
#pragma unroll
                for (int j = 0; j < 4; j++) sc[i][j] = 0.0f;

#pragma unroll
            for (int q = 0; q < 4; q++) {
                int nt = c * 4 + q;
                int brow = nt * 8 + ri;
                uint32_t r4[4], bh[4][2];
                ldm4(r4, su + SWZ(brow * 128 + g8 * 16));
                bh[0][0] = r4[0]; bh[0][1] = r4[1]; bh[1][0] = r4[2]; bh[1][1] = r4[3];
                ldm4(r4, su + SWZ(brow * 128 + 64 + g8 * 16));
                bh[2][0] = r4[0]; bh[2][1] = r4[1]; bh[3][0] = r4[2]; bh[3][1] = r4[3];
#pragma unroll
                for (int ks = 0; ks < 4; ks++) mma16816(sc[q], qh[ks], bh[ks]);
            }

            uint32_t pf[4][2];
#pragma unroll
            for (int q = 0; q < 4; q++) {
                float e0 = ex2f(sc[q][0] * CEXP);
                float e1 = ex2f(sc[q][1] * CEXP);
                float e2 = ex2f(sc[q][2] * CEXP);
                float e3 = ex2f(sc[q][3] * CEXP);
                lsum0 += e0 + e1;
                lsum1 += e2 + e3;
                pf[q][0] = cvt_f16x2(e1, e0);
                pf[q][1] = cvt_f16x2(e3, e2);
            }

#pragma unroll
            for (int jj = 0; jj < 2; jj++) {
                uint32_t pa[4] = { pf[2 * jj][0], pf[2 * jj][1],
                                   pf[2 * jj + 1][0], pf[2 * jj + 1][1] };
                int vrow = (c * 2 + jj) * 16 + ((g8 & 1) << 3) + ri;
#pragma unroll
                for (int nvp = 0; nvp < 4; nvp++) {
                    int vchunk = nvp * 16 + ((g8 >> 1) << 3);
                    uint32_t r4[4];
                    ldm4t(r4, su + OFF_V + SWZ(vrow * 128 + vchunk * 2));
                    mma16816h(o16[nvp * 2 + 0], pa, r4 + 0);
                    mma16816h(o16[nvp * 2 + 1], pa, r4 + 2);
                }
            }
        }

        // ---- flush fp16 tile accumulators into fp32 master
#pragma unroll
        for (int nv = 0; nv < 8; nv++) {
            float2 f0 = __half22float2(*reinterpret_cast<__half2*>(&o16[nv][0]));
            float2 f1 = __half22float2(*reinterpret_cast<__half2*>(&o16[nv][1]));
            o_acc[nv][0] += f0.x; o_acc[nv][1] += f0.y;
            o_acc[nv][2] += f1.x; o_acc[nv][3] += f1.y;
        }
        // no trailing barrier: 3-stage rotation keeps readers/writers disjoint
    }

    // ---- finalize (fp16 output only)
    lsum0 += __shfl_xor_sync(0xffffffffu, lsum0, 1);
    lsum0 += __shfl_xor_sync(0xffffffffu, lsum0, 2);
    lsum1 += __shfl_xor_sync(0xffffffffu, lsum1, 1);
    lsum1 += __shfl_xor_sync(0xffffffffu, lsum1, 2);
    const float inv0 = 1.0f / lsum0;
    const float inv1 = 1.0f / lsum1;

    const int wr0 = q0 + wid * 16 + gid;
    size_t base0 = ((size_t)(b * NN + wr0)) * DD + h * HD;
    size_t base1 = base0 + (size_t)8 * DD;
#pragma unroll
    for (int nv = 0; nv < 8; nv++) {
        int col = nv * 8 + tig * 2;
        *reinterpret_cast<uint32_t*>(g_ah + base0 + col) =
            cvt_f16x2(o_acc[nv][1] * inv0, o_acc[nv][0] * inv0);
        *reinterpret_cast<uint32_t*>(g_ah + base1 + col) =
            cvt_f16x2(o_acc[nv][3] * inv1, o_acc[nv][2] * inv1);
    }
}

// ---------------------------------------------------------------------------
// Projection: C[m][n] = A[m][:] . W[n][:] + bias[n], single-pass fp16 mma.
// 64x64 tiles: grid (8, 128) = 1024 CTAs, block 128 (4 warps, 32x32 each).
// k-chunk 64. smem: 2 stages x {A 8K, W 8K} = 32 KB -> 4 CTAs/SM.
// ---------------------------------------------------------------------------
#define PSTG 16384
#define POFF_W 8192

__global__ __launch_bounds__(128, 4)
void proj4_kernel(const float* __restrict__ bias, float* __restrict__ C)
{
    extern __shared__ char smem[];
    const uint32_t sb = smem_u32(smem);
    const int tid  = threadIdx.x;
    const int wid  = tid >> 5;
    const int lane = tid & 31;
    const int gid  = lane >> 2;
    const int tig  = lane & 3;
    const int g8   = lane >> 3;
    const int ri   = lane & 7;
    const int n0 = blockIdx.x * 64;
    const int m0 = blockIdx.y * 64;
    const int warp_m = (wid >> 1) * 32;
    const int warp_n = (wid & 1) * 32;

    // k-chunk = 64 halves = 128 B/row; A 64 rows + W 64 rows = 1024 16B chunks
#define PLOAD(kc, s) do { \
    uint32_t _sb2 = sb + (s) * PSTG; \
    _Pragma("unroll") \
    for (int _i = 0; _i < 4; _i++) { \
        int _slot = _i * 128 + tid; \
        int _row = _slot >> 3, _c8 = _slot & 7; \
        cpa16(_sb2 + SWZ(_row * 128 + _c8 * 16), \
              g_ah + (size_t)(m0 + _row) * DD + (kc) * 64 + _c8 * 8); \
    } \
    _Pragma("unroll") \
    for (int _i = 0; _i < 4; _i++) { \
        int _slot = _i * 128 + tid; \
        int _row = _slot >> 3, _c8 = _slot & 7; \
        cpa16(_sb2 + POFF_W + SWZ(_row * 128 + _c8 * 16), \
              g_wh + (size_t)(n0 + _row) * DD + (kc) * 64 + _c8 * 8); \
    } \
    CPC(); } while (0)

    float acc[2][4][4];
#pragma unroll
    for (int m = 0; m < 2; m++)
#pragma unroll
        for (int nb = 0; nb < 4; nb++)
#pragma unroll
            for (int j = 0; j < 4; j++) acc[m][nb][j] = 0.0f;

    PLOAD(0, 0);
    PLOAD(1, 1);

    for (int kc = 0; kc < 8; kc++) {
        if (kc == 7) { CPW0(); } else { CPW1(); }
        __syncthreads();
        const uint32_t su = sb + (kc & 1) * PSTG;

        uint32_t ah[2][4][4];
#pragma unroll
        for (int m = 0; m < 2; m++) {
            int arow = warp_m + m * 16 + ((g8 & 1) << 3) + ri;
#pragma unroll
            for (int ks = 0; ks < 4; ks++) {
                ldm4(ah[m][ks], su + SWZ(arow * 128 + ks * 32 + ((g8 >> 1) << 4)));
            }
        }
#pragma unroll
        for (int nb = 0; nb < 4; nb++) {
            int brow = warp_n + nb * 8 + ri;
            uint32_t w0[4], w1[4];
            ldm4(w0, su + POFF_W + SWZ(brow * 128 + g8 * 16));
            ldm4(w1, su + POFF_W + SWZ(brow * 128 + 64 + g8 * 16));
#pragma unroll
            for (int m = 0; m < 2; m++) {
                mma16816(acc[m][nb], ah[m][0], w0 + 0);
                mma16816(acc[m][nb], ah[m][1], w0 + 2);
                mma16816(acc[m][nb], ah[m][2], w1 + 0);
                mma16816(acc[m][nb], ah[m][3], w1 + 2);
            }
        }
        __syncthreads();
        if (kc + 2 < 8) PLOAD(kc + 2, kc & 1);
    }

#pragma unroll
    for (int m = 0; m < 2; m++) {
        int r0 = m0 + warp_m + m * 16 + gid;
#pragma unroll
        for (int nb = 0; nb < 4; nb++) {
            int col = n0 + warp_n + nb * 8 + tig * 2;
            float2 bv = *reinterpret_cast<const float2*>(bias + col);
            float2 v0 = make_float2(acc[m][nb][0] + bv.x, acc[m][nb][1] + bv.y);
            float2 v1 = make_float2(acc[m][nb][2] + bv.x, acc[m][nb][3] + bv.y);
            *reinterpret_cast<float2*>(C + (size_t)r0 * DD + col) = v0;
            *reinterpret_cast<float2*>(C + (size_t)(r0 + 8) * DD + col) = v1;
        }
    }
}

// ---------------------------------------------------------------------------
extern "C" void kernel_launch(void* const* d_in, const int* in_sizes, int n_in,
                              void* d_out, int out_size)
{
    const float* keys    = (const float*)d_in[0];
    const float* queries = (const float*)d_in[1];
    const float* values  = (const float*)d_in[2];
    const float* W_comb  = (const float*)d_in[3];
    const float* b_comb  = (const float*)d_in[4];
    float* out = (float*)d_out;

    cudaFuncSetAttribute(attn2_kernel,
                         cudaFuncAttributeMaxDynamicSharedMemorySize, 3 * ASTG);
    cudaFuncSetAttribute(proj4_kernel,
                         cudaFuncAttributeMaxDynamicSharedMemorySize, 2 * PSTG);

    prep_kernel<<<dim3(2048, 4), 256>>>(keys, queries, values, W_comb);

    dim3 agrid(NN / TQ, HH, BB);
    attn2_kernel<<<agrid, 256, 3 * ASTG>>>();

    dim3 pgrid(DD / 64, (BB * NN) / 64);
    proj4_kernel<<<pgrid, 128, 2 * PSTG>>>(b_comb, out);
}

// round 16
// speedup vs baseline: 1.5784x; 1.0618x over previous
#include <cuda_runtime.h>
#include <cuda_fp16.h>
#include <cstdint>

// ---------------------------------------------------------------------------
// Problem constants
// ---------------------------------------------------------------------------
#define BB 4
#define NN 2048
#define DD 512
#define HH 8
#define HD 64
#define TQ 128           // queries per CTA
#define TK 128           // keys per tile
#define NTILES (NN / TK) // 16

// exp(S/TEMP) = 2^(S * log2(e)/8)
#define CEXP 0.1803368801111244f

typedef unsigned long long u64;

// fp16 staging buffers (per-head contiguous layout: [(b*HH+h), n, hd])
__device__ __half g_kh[(size_t)BB * HH * NN * HD];
__device__ __half g_vh[(size_t)BB * HH * NN * HD];
// attention output fp16: [(b*NN + n), d]
__device__ __half g_ah[(size_t)BB * NN * DD];
// W fp16 [n][k]
__device__ __half g_wh[(size_t)DD * DD];

#define SWZ(o) ((o) ^ (((o) >> 3) & 0x70))

// ---------------------------------------------------------------------------
// PTX helpers
// ---------------------------------------------------------------------------
__device__ __forceinline__ uint32_t smem_u32(const void* p) {
    uint32_t a;
    asm("{ .reg .u64 t; cvta.to.shared.u64 t, %1; cvt.u32.u64 %0, t; }" : "=r"(a) : "l"(p));
    return a;
}
__device__ __forceinline__ float ex2f(float x) {
    float y; asm("ex2.approx.f32 %0, %1;" : "=f"(y) : "f"(x)); return y;
}
__device__ __forceinline__ uint32_t cvt_f16x2(float hi, float lo) {
    uint32_t r; asm("cvt.rn.f16x2.f32 %0, %1, %2;" : "=r"(r) : "f"(hi), "f"(lo)); return r;
}
__device__ __forceinline__ void ldm4(uint32_t* r, uint32_t addr) {
    asm volatile("ldmatrix.sync.aligned.m8n8.x4.shared.b16 {%0,%1,%2,%3}, [%4];"
        : "=r"(r[0]), "=r"(r[1]), "=r"(r[2]), "=r"(r[3]) : "r"(addr));
}
__device__ __forceinline__ void ldm4t(uint32_t* r, uint32_t addr) {
    asm volatile("ldmatrix.sync.aligned.m8n8.x4.trans.shared.b16 {%0,%1,%2,%3}, [%4];"
        : "=r"(r[0]), "=r"(r[1]), "=r"(r[2]), "=r"(r[3]) : "r"(addr));
}
__device__ __forceinline__ void mma16816(float* c, const uint32_t* a, const uint32_t* b) {
    asm volatile("mma.sync.aligned.m16n8k16.row.col.f32.f16.f16.f32 "
        "{%0,%1,%2,%3}, {%4,%5,%6,%7}, {%8,%9}, {%0,%1,%2,%3};"
        : "+f"(c[0]), "+f"(c[1]), "+f"(c[2]), "+f"(c[3])
        : "r"(a[0]), "r"(a[1]), "r"(a[2]), "r"(a[3]), "r"(b[0]), "r"(b[1]));
}
__device__ __forceinline__ void cpa16(uint32_t dst, const void* src) {
    asm volatile("cp.async.cg.shared.global [%0], [%1], 16;"
        :: "r"(dst), "l"(__cvta_generic_to_global(src)) : "memory");
}
#define CPC()  asm volatile("cp.async.commit_group;" ::: "memory")
#define CPW0() asm volatile("cp.async.wait_group 0;" ::: "memory")
#define CPW1() asm volatile("cp.async.wait_group 1;" ::: "memory")

// ---------------------------------------------------------------------------
// Prep: fp32 -> fp16 conversion + per-head relayout for K, V; W flat.
// grid (2048, 3), block 256. blockIdx.y: 0=K, 1=V, 2=W (first 128 blocks).
// 2 float4 per thread.
// ---------------------------------------------------------------------------
__global__ __launch_bounds__(256)
void prep_kernel(const float* __restrict__ Kg, const float* __restrict__ Vg,
                 const float* __restrict__ Wg)
{
    int t = blockIdx.y;
    if (t == 2) {
        if (blockIdx.x >= 128) return;
        int i0 = blockIdx.x * 512 + threadIdx.x * 2;
#pragma unroll
        for (int j = 0; j < 2; j++) {
            int i = i0 + j;
            float4 v = reinterpret_cast<const float4*>(Wg)[i];
            __half2 hA = __halves2half2(__float2half_rn(v.x), __float2half_rn(v.y));
            __half2 hB = __halves2half2(__float2half_rn(v.z), __float2half_rn(v.w));
            *reinterpret_cast<uint2*>(g_wh + (size_t)i * 4) =
                make_uint2(*reinterpret_cast<uint32_t*>(&hA),
                           *reinterpret_cast<uint32_t*>(&hB));
        }
        return;
    }
    const float* src = (t == 0) ? Kg : Vg;
    __half* dst = (t == 0) ? g_kh : g_vh;
    int i0 = blockIdx.x * 512 + threadIdx.x * 2;
#pragma unroll
    for (int j = 0; j < 2; j++) {
        int i = i0 + j;
        float4 v = reinterpret_cast<const float4*>(src)[i];
        int d4 = i & 127, n = (i >> 7) & 2047, b = i >> 18;
        int h = d4 >> 4, hd4 = d4 & 15;
        size_t o = ((((size_t)b * HH + h) * NN + n) * HD + hd4 * 4);
        __half2 hA = __halves2half2(__float2half_rn(v.x), __float2half_rn(v.y));
        __half2 hB = __halves2half2(__float2half_rn(v.z), __float2half_rn(v.w));
        *reinterpret_cast<uint2*>(dst + o) =
            make_uint2(*reinterpret_cast<uint32_t*>(&hA),
                       *reinterpret_cast<uint32_t*>(&hB));
    }
}

// ---------------------------------------------------------------------------
// Attention: mma.sync + 3-stage cp.async pipeline, fp16 QK + fp32-accum PV.
// Q converted from fp32 in-kernel (each Q element used by exactly one CTA).
// grid (16, 8, 4), block 256 (8 warps, 16 q-rows each).
// smem: 3 stages x {k 16K, v 16K} = 96 KB -> 2 CTAs/SM.
// ---------------------------------------------------------------------------
#define ASTG 32768
#define OFF_V 16384

__global__ __launch_bounds__(256, 2)
void attn2_kernel(const float* __restrict__ Qg)
{
    extern __shared__ char smem[];
    const uint32_t sb = smem_u32(smem);
    const int tid  = threadIdx.x;
    const int wid  = tid >> 5;
    const int lane = tid & 31;
    const int gid  = lane >> 2;
    const int tig  = lane & 3;
    const int g8   = lane >> 3;
    const int ri   = lane & 7;
    const int q0 = blockIdx.x * TQ;
    const int h  = blockIdx.y;
    const int b  = blockIdx.z;

    const size_t hb = (((size_t)b) * HH + h) * NN * HD;  // head base (halves)

    // ---- load fp32 Q tile, convert to fp16 into stage-0 K buffer
    {
        const float* qg = Qg + ((size_t)(b * NN + q0)) * DD + h * HD;
#pragma unroll
        for (int s8 = 0; s8 < 8; s8++) {
            int slot = s8 * 256 + tid;       // 0..2047 float4 slots
            int row = slot >> 4, c4 = slot & 15;
            float4 v = *reinterpret_cast<const float4*>(qg + (size_t)row * DD + c4 * 4);
            int bo = row * 128 + c4 * 8;
            __half2 hA = __halves2half2(__float2half_rn(v.x), __float2half_rn(v.y));
            __half2 hB = __halves2half2(__float2half_rn(v.z), __float2half_rn(v.w));
            *reinterpret_cast<uint2*>(smem + SWZ(bo)) =
                make_uint2(*reinterpret_cast<uint32_t*>(&hA),
                           *reinterpret_cast<uint32_t*>(&hB));
        }
    }
    __syncthreads();

    uint32_t qh[4][4];
    {
        int arow = wid * 16 + ((g8 & 1) << 3) + ri;
        int acol = (g8 >> 1) << 3;
#pragma unroll
        for (int ks = 0; ks < 4; ks++) {
            int co = (ks * 16 + acol) * 2;
            ldm4(qh[ks], sb + SWZ(arow * 128 + co));
        }
    }
    __syncthreads();

    float o_acc[8][4];
#pragma unroll
    for (int i = 0; i < 8; i++)
#pragma unroll
        for (int j = 0; j < 4; j++) o_acc[i][j] = 0.0f;
    float lsum0 = 0.0f, lsum1 = 0.0f;

#define LOADTILE(t, s) do { \
    const __half* _kh = g_kh + hb + (size_t)(t) * TK * HD; \
    const __half* _vh = g_vh + hb + (size_t)(t) * TK * HD; \
    uint32_t _sb2 = sb + (s) * ASTG; \
    _Pragma("unroll") \
    for (int _i = 0; _i < 4; _i++) { \
        int _ch = _i * 256 + tid; \
        uint32_t _d = SWZ(_ch * 16); \
        cpa16(_sb2 + _d, _kh + _ch * 8); \
        cpa16(_sb2 + OFF_V + _d, _vh + _ch * 8); \
    } \
    CPC(); } while (0)

    LOADTILE(0, 0);
    LOADTILE(1, 1);

    for (int t = 0; t < NTILES; t++) {
        if (t == NTILES - 1) { CPW0(); } else { CPW1(); }
        __syncthreads();
        if (t + 2 < NTILES) LOADTILE(t + 2, (t + 2) % 3);
        const uint32_t su = sb + (t % 3) * ASTG;

#pragma unroll
        for (int c = 0; c < 4; c++) {
            float sc[4][4];
#pragma unroll
            for (int i = 0; i < 4; i++)
#pragma unroll
                for (int j = 0; j < 4; j++) sc[i][j] = 0.0f;

#pragma unroll
            for (int q = 0; q < 4; q++) {
                int nt = c * 4 + q;
                int brow = nt * 8 + ri;
                uint32_t r4[4], bh[4][2];
                ldm4(r4, su + SWZ(brow * 128 + g8 * 16));
                bh[0][0] = r4[0]; bh[0][1] = r4[1]; bh[1][0] = r4[2]; bh[1][1] = r4[3];
                ldm4(r4, su + SWZ(brow * 128 + 64 + g8 * 16));
                bh[2][0] = r4[0]; bh[2][1] = r4[1]; bh[3][0] = r4[2]; bh[3][1] = r4[3];
#pragma unroll
                for (int ks = 0; ks < 4; ks++) mma16816(sc[q], qh[ks], bh[ks]);
            }

            uint32_t pf[4][2];
#pragma unroll
            for (int q = 0; q < 4; q++) {
                float e0 = ex2f(sc[q][0] * CEXP);
                float e1 = ex2f(sc[q][1] * CEXP);
                float e2 = ex2f(sc[q][2] * CEXP);
                float e3 = ex2f(sc[q][3] * CEXP);
                lsum0 += e0 + e1;
                lsum1 += e2 + e3;
                pf[q][0] = cvt_f16x2(e1, e0);
                pf[q][1] = cvt_f16x2(e3, e2);
            }

#pragma unroll
            for (int jj = 0; jj < 2; jj++) {
                uint32_t pa[4] = { pf[2 * jj][0], pf[2 * jj][1],
                                   pf[2 * jj + 1][0], pf[2 * jj + 1][1] };
                int vrow = (c * 2 + jj) * 16 + ((g8 & 1) << 3) + ri;
#pragma unroll
                for (int nvp = 0; nvp < 4; nvp++) {
                    int vchunk = nvp * 16 + ((g8 >> 1) << 3);
                    uint32_t r4[4];
                    ldm4t(r4, su + OFF_V + SWZ(vrow * 128 + vchunk * 2));
                    mma16816(o_acc[nvp * 2 + 0], pa, r4 + 0);
                    mma16816(o_acc[nvp * 2 + 1], pa, r4 + 2);
                }
            }
        }
        // no trailing barrier: 3-stage rotation keeps readers/writers disjoint
    }

    // ---- finalize (fp16 output only)
    lsum0 += __shfl_xor_sync(0xffffffffu, lsum0, 1);
    lsum0 += __shfl_xor_sync(0xffffffffu, lsum0, 2);
    lsum1 += __shfl_xor_sync(0xffffffffu, lsum1, 1);
    lsum1 += __shfl_xor_sync(0xffffffffu, lsum1, 2);
    const float inv0 = 1.0f / lsum0;
    const float inv1 = 1.0f / lsum1;

    const int wr0 = q0 + wid * 16 + gid;
    size_t base0 = ((size_t)(b * NN + wr0)) * DD + h * HD;
    size_t base1 = base0 + (size_t)8 * DD;
#pragma unroll
    for (int nv = 0; nv < 8; nv++) {
        int col = nv * 8 + tig * 2;
        *reinterpret_cast<uint32_t*>(g_ah + base0 + col) =
            cvt_f16x2(o_acc[nv][1] * inv0, o_acc[nv][0] * inv0);
        *reinterpret_cast<uint32_t*>(g_ah + base1 + col) =
            cvt_f16x2(o_acc[nv][3] * inv1, o_acc[nv][2] * inv1);
    }
}

// ---------------------------------------------------------------------------
// Projection: C[m][n] = A[m][:] . W[n][:] + bias[n], single-pass fp16 mma.
// 64x64 tiles: grid (8, 128) = 1024 CTAs, block 128 (4 warps, 32x32 each).
// k-chunk 64. smem: 2 stages x {A 8K, W 8K} = 32 KB -> 4 CTAs/SM.
// ---------------------------------------------------------------------------
#define PSTG 16384
#define POFF_W 8192

__global__ __launch_bounds__(128, 4)
void proj4_kernel(const float* __restrict__ bias, float* __restrict__ C)
{
    extern __shared__ char smem[];
    const uint32_t sb = smem_u32(smem);
    const int tid  = threadIdx.x;
    const int wid  = tid >> 5;
    const int lane = tid & 31;
    const int gid  = lane >> 2;
    const int tig  = lane & 3;
    const int g8   = lane >> 3;
    const int ri   = lane & 7;
    const int n0 = blockIdx.x * 64;
    const int m0 = blockIdx.y * 64;
    const int warp_m = (wid >> 1) * 32;
    const int warp_n = (wid & 1) * 32;

    // k-chunk = 64 halves = 128 B/row; A 64 rows + W 64 rows = 1024 16B chunks
#define PLOAD(kc, s) do { \
    uint32_t _sb2 = sb + (s) * PSTG; \
    _Pragma("unroll") \
    for (int _i = 0; _i < 4; _i++) { \
        int _slot = _i * 128 + tid; \
        int _row = _slot >> 3, _c8 = _slot & 7; \
        cpa16(_sb2 + SWZ(_row * 128 + _c8 * 16), \
              g_ah + (size_t)(m0 + _row) * DD + (kc) * 64 + _c8 * 8); \
    } \
    _Pragma("unroll") \
    for (int _i = 0; _i < 4; _i++) { \
        int _slot = _i * 128 + tid; \
        int _row = _slot >> 3, _c8 = _slot & 7; \
        cpa16(_sb2 + POFF_W + SWZ(_row * 128 + _c8 * 16), \
              g_wh + (size_t)(n0 + _row) * DD + (kc) * 64 + _c8 * 8); \
    } \
    CPC(); } while (0)

    float acc[2][4][4];
#pragma unroll
    for (int m = 0; m < 2; m++)
#pragma unroll
        for (int nb = 0; nb < 4; nb++)
#pragma unroll
            for (int j = 0; j < 4; j++) acc[m][nb][j] = 0.0f;

    PLOAD(0, 0);
    PLOAD(1, 1);

    for (int kc = 0; kc < 8; kc++) {
        if (kc == 7) { CPW0(); } else { CPW1(); }
        __syncthreads();
        const uint32_t su = sb + (kc & 1) * PSTG;

        uint32_t ah[2][4][4];
#pragma unroll
        for (int m = 0; m < 2; m++) {
            int arow = warp_m + m * 16 + ((g8 & 1) << 3) + ri;
#pragma unroll
            for (int ks = 0; ks < 4; ks++) {
                ldm4(ah[m][ks], su + SWZ(arow * 128 + ks * 32 + ((g8 >> 1) << 4)));
            }
        }
#pragma unroll
        for (int nb = 0; nb < 4; nb++) {
            int brow = warp_n + nb * 8 + ri;
            uint32_t w0[4], w1[4];
            ldm4(w0, su + POFF_W + SWZ(brow * 128 + g8 * 16));
            ldm4(w1, su + POFF_W + SWZ(brow * 128 + 64 + g8 * 16));
#pragma unroll
            for (int m = 0; m < 2; m++) {
                mma16816(acc[m][nb], ah[m][0], w0 + 0);
                mma16816(acc[m][nb], ah[m][1], w0 + 2);
                mma16816(acc[m][nb], ah[m][2], w1 + 0);
                mma16816(acc[m][nb], ah[m][3], w1 + 2);
            }
        }
        __syncthreads();
        if (kc + 2 < 8) PLOAD(kc + 2, kc & 1);
    }

#pragma unroll
    for (int m = 0; m < 2; m++) {
        int r0 = m0 + warp_m + m * 16 + gid;
#pragma unroll
        for (int nb = 0; nb < 4; nb++) {
            int col = n0 + warp_n + nb * 8 + tig * 2;
            float2 bv = *reinterpret_cast<const float2*>(bias + col);
            float2 v0 = make_float2(acc[m][nb][0] + bv.x, acc[m][nb][1] + bv.y);
            float2 v1 = make_float2(acc[m][nb][2] + bv.x, acc[m][nb][3] + bv.y);
            *reinterpret_cast<float2*>(C + (size_t)r0 * DD + col) = v0;
            *reinterpret_cast<float2*>(C + (size_t)(r0 + 8) * DD + col) = v1;
        }
    }
}

// ---------------------------------------------------------------------------
extern "C" void kernel_launch(void* const* d_in, const int* in_sizes, int n_in,
                              void* d_out, int out_size)
{
    const float* keys    = (const float*)d_in[0];
    const float* queries = (const float*)d_in[1];
    const float* values  = (const float*)d_in[2];
    const float* W_comb  = (const float*)d_in[3];
    const float* b_comb  = (const float*)d_in[4];
    float* out = (float*)d_out;

    cudaFuncSetAttribute(attn2_kernel,
                         cudaFuncAttributeMaxDynamicSharedMemorySize, 3 * ASTG);
    cudaFuncSetAttribute(proj4_kernel,
                         cudaFuncAttributeMaxDynamicSharedMemorySize, 2 * PSTG);

    prep_kernel<<<dim3(2048, 3), 256>>>(keys, values, W_comb);

    dim3 agrid(NN / TQ, HH, BB);
    attn2_kernel<<<agrid, 256, 3 * ASTG>>>(queries);

    dim3 pgrid(DD / 64, (BB * NN) / 64);
    proj4_kernel<<<pgrid, 128, 2 * PSTG>>>(b_comb, out);
}